// round 16
// baseline (speedup 1.0000x reference)
#include <cuda_runtime.h>
#include <cuda_fp16.h>
#include <cstdint>
#include <cfloat>

#define NN 50000
#define FIN 512
#define H1C 64     // 8 heads * 8
#define H2C 40     // 1 head * 40
#define EMAX 1700000

// ---------------- scratch (device globals; no allocation allowed) -------------
__device__ int    g_esrc[EMAX + NN];   // src sorted by dst (CSR payload)
__device__ int    g_deg[NN];           // in-degree histogram
__device__ int    g_rowp[NN + 1];      // CSR row pointers
__device__ int    g_pos[NN];           // scatter cursors
__device__ __half g_h1h[NN * H1C];     // x @ W1 (fp16 messages)
__device__ float  g_as1[NN * 8];       // a_src layer1 (fp32)
__device__ float  g_ad1[NN * 8];       // a_dst layer1 (fp32)
__device__ float  g_out1[NN * H1C];    // relu(agg1 + b1), fp32
__device__ __half g_h2h[NN * H2C];     // out1 @ W2 (fp16 messages)
__device__ float  g_as2[NN];
__device__ float  g_ad2[NN];

__device__ __forceinline__ float lrelu_exp(float e) {
    e = (e < 0.f) ? 0.2f * e : e;
    return __expf(e);
}

__device__ __forceinline__ unsigned f2tf32(float f) {
    unsigned r;
    asm("cvt.rna.tf32.f32 %0, %1;" : "=r"(r) : "f"(f));
    return r;
}

__device__ __forceinline__ void mma_tf32(float* d, const unsigned* a, unsigned b0, unsigned b1) {
    asm volatile(
        "mma.sync.aligned.m16n8k8.row.col.f32.tf32.tf32.f32 "
        "{%0,%1,%2,%3}, {%4,%5,%6,%7}, {%8,%9}, {%0,%1,%2,%3};"
        : "+f"(d[0]), "+f"(d[1]), "+f"(d[2]), "+f"(d[3])
        : "r"(a[0]), "r"(a[1]), "r"(a[2]), "r"(a[3]), "r"(b0), "r"(b1));
}

// ---------------- CSR build ----------------------------------------------------
// histogram of dst; 8 edges per thread for deep MLP
__global__ void k_decode(const int* __restrict__ w, int E) {
    bool is64 = (w[1] == 0 && w[3] == 0 && w[5] == 0 && w[7] == 0);
    int i8 = (blockIdx.x * blockDim.x + threadIdx.x) * 8;
    int ET = E + NN;
    if (i8 >= ET) return;
    if (i8 + 7 < E) {
        int d[8];
        if (is64) {
            const long long* p = (const long long*)w + E + i8;
            longlong2 a = *(const longlong2*)(p);
            longlong2 b = *(const longlong2*)(p + 2);
            longlong2 cc = *(const longlong2*)(p + 4);
            longlong2 dd = *(const longlong2*)(p + 6);
            d[0] = (int)a.x;  d[1] = (int)a.y;  d[2] = (int)b.x;  d[3] = (int)b.y;
            d[4] = (int)cc.x; d[5] = (int)cc.y; d[6] = (int)dd.x; d[7] = (int)dd.y;
        } else {
            int4 v0 = *(const int4*)(w + E + i8);
            int4 v1 = *(const int4*)(w + E + i8 + 4);
            d[0] = v0.x; d[1] = v0.y; d[2] = v0.z; d[3] = v0.w;
            d[4] = v1.x; d[5] = v1.y; d[6] = v1.z; d[7] = v1.w;
        }
#pragma unroll
        for (int k = 0; k < 8; k++) atomicAdd(&g_deg[d[k]], 1);
    } else {
        for (int i = i8; i < i8 + 8 && i < ET; i++) {
            int d;
            if (i >= E) d = i - E;
            else if (is64) d = (int)((const long long*)w)[E + i];
            else d = w[E + i];
            atomicAdd(&g_deg[d], 1);
        }
    }
}

// single-block exclusive scan of g_deg -> g_rowp, g_pos
__global__ void k_scan(int ET) {
    __shared__ int sh[1024];
    int t = threadIdx.x;
    const int CH = (NN + 1023) / 1024;     // 49
    int b = t * CH;
    int e = b + CH; if (e > NN) e = NN; if (b > NN) b = NN;
    int s = 0;
    for (int i = b; i < e; i++) s += g_deg[i];
    sh[t] = s;
    __syncthreads();
    for (int off = 1; off < 1024; off <<= 1) {
        int v = (t >= off) ? sh[t - off] : 0;
        __syncthreads();
        sh[t] += v;
        __syncthreads();
    }
    int run = sh[t] - s;                   // exclusive prefix
    for (int i = b; i < e; i++) {
        int d = g_deg[i];
        g_rowp[i] = run;
        g_pos[i]  = run;
        run += d;
    }
    if (t == 1023) g_rowp[NN] = ET;
}

// scatter src into CSR slots; 8 edges per thread
__global__ void k_scatter(const int* __restrict__ w, int E) {
    bool is64 = (w[1] == 0 && w[3] == 0 && w[5] == 0 && w[7] == 0);
    int i8 = (blockIdx.x * blockDim.x + threadIdx.x) * 8;
    int ET = E + NN;
    if (i8 >= ET) return;
    if (i8 + 7 < E) {
        int s[8], d[8];
        if (is64) {
            const long long* ps = (const long long*)w + i8;
            const long long* pd = (const long long*)w + E + i8;
#pragma unroll
            for (int k = 0; k < 4; k++) {
                longlong2 sv = *(const longlong2*)(ps + 2 * k);
                longlong2 dv = *(const longlong2*)(pd + 2 * k);
                s[2 * k] = (int)sv.x; s[2 * k + 1] = (int)sv.y;
                d[2 * k] = (int)dv.x; d[2 * k + 1] = (int)dv.y;
            }
        } else {
            int4 s0 = *(const int4*)(w + i8);
            int4 s1 = *(const int4*)(w + i8 + 4);
            int4 d0 = *(const int4*)(w + E + i8);
            int4 d1 = *(const int4*)(w + E + i8 + 4);
            s[0] = s0.x; s[1] = s0.y; s[2] = s0.z; s[3] = s0.w;
            s[4] = s1.x; s[5] = s1.y; s[6] = s1.z; s[7] = s1.w;
            d[0] = d0.x; d[1] = d0.y; d[2] = d0.z; d[3] = d0.w;
            d[4] = d1.x; d[5] = d1.y; d[6] = d1.z; d[7] = d1.w;
        }
        int p[8];
#pragma unroll
        for (int k = 0; k < 8; k++) p[k] = atomicAdd(&g_pos[d[k]], 1);
#pragma unroll
        for (int k = 0; k < 8; k++) g_esrc[p[k]] = s[k];
    } else {
        for (int i = i8; i < i8 + 8 && i < ET; i++) {
            int s, d;
            if (i >= E) { s = d = i - E; }
            else if (is64) {
                const long long* e64 = (const long long*)w;
                s = (int)e64[i]; d = (int)e64[E + i];
            } else {
                s = w[i]; d = w[E + i];
            }
            int p = atomicAdd(&g_pos[d], 1);
            g_esrc[p] = s;
        }
    }
}

// ---------------- GEMM1 (tf32 tensor cores): h1 = x @ W1, fused a1 ------------
__global__ void k_gemm1(const float* __restrict__ x, const float* __restrict__ W,
                        const float* __restrict__ attS, const float* __restrict__ attD) {
    __shared__ unsigned As[16][264];   // [k][m] tf32
    __shared__ unsigned Bs[16][72];    // [k][n] tf32
    int t = threadIdx.x;
    int warp = t >> 5, lane = t & 31;
    int g = lane >> 2, q = lane & 3;
    int m0 = blockIdx.x * 256;

    float acc[2][8][4];
#pragma unroll
    for (int mt = 0; mt < 2; mt++)
#pragma unroll
        for (int n8 = 0; n8 < 8; n8++)
#pragma unroll
            for (int i = 0; i < 4; i++) acc[mt][n8][i] = 0.f;

    int lm = t >> 2;
    int lkq = t & 3;
    int bk = t >> 4;
    int bn = t & 15;

    for (int k0 = 0; k0 < FIN; k0 += 16) {
#pragma unroll
        for (int it = 0; it < 4; it++) {
            int m = lm + 64 * it;
            int gm = m0 + m;
            float4 v = make_float4(0.f, 0.f, 0.f, 0.f);
            if (gm < NN) v = *(const float4*)(x + (size_t)gm * FIN + k0 + 4 * lkq);
            As[4 * lkq + 0][m] = f2tf32(v.x);
            As[4 * lkq + 1][m] = f2tf32(v.y);
            As[4 * lkq + 2][m] = f2tf32(v.z);
            As[4 * lkq + 3][m] = f2tf32(v.w);
        }
        {
            float4 v = *(const float4*)(W + (size_t)(k0 + bk) * 64 + 4 * bn);
            Bs[bk][4 * bn + 0] = f2tf32(v.x);
            Bs[bk][4 * bn + 1] = f2tf32(v.y);
            Bs[bk][4 * bn + 2] = f2tf32(v.z);
            Bs[bk][4 * bn + 3] = f2tf32(v.w);
        }
        __syncthreads();

#pragma unroll
        for (int kk = 0; kk < 16; kk += 8) {
            unsigned a[2][4];
#pragma unroll
            for (int mt = 0; mt < 2; mt++) {
                int r = warp * 32 + 16 * mt + g;
                a[mt][0] = As[kk + q][r];
                a[mt][1] = As[kk + q][r + 8];
                a[mt][2] = As[kk + q + 4][r];
                a[mt][3] = As[kk + q + 4][r + 8];
            }
#pragma unroll
            for (int n8 = 0; n8 < 8; n8++) {
                unsigned b0 = Bs[kk + q][8 * n8 + g];
                unsigned b1 = Bs[kk + q + 4][8 * n8 + g];
                mma_tf32(acc[0][n8], a[0], b0, b1);
                mma_tf32(acc[1][n8], a[1], b0, b1);
            }
        }
        __syncthreads();
    }

#pragma unroll
    for (int mt = 0; mt < 2; mt++) {
        int rlo = m0 + warp * 32 + 16 * mt + g;
        int rhi = rlo + 8;
#pragma unroll
        for (int n8 = 0; n8 < 8; n8++) {
            float c0 = acc[mt][n8][0], c1 = acc[mt][n8][1];
            float c2 = acc[mt][n8][2], c3 = acc[mt][n8][3];
            int col = 8 * n8 + 2 * q;
            if (rlo < NN) *(__half2*)(g_h1h + (size_t)rlo * 64 + col) = __floats2half2_rn(c0, c1);
            if (rhi < NN) *(__half2*)(g_h1h + (size_t)rhi * 64 + col) = __floats2half2_rn(c2, c3);
            float aS0 = __ldg(attS + col), aS1 = __ldg(attS + col + 1);
            float aD0 = __ldg(attD + col), aD1 = __ldg(attD + col + 1);
            float sLo = c0 * aS0 + c1 * aS1;
            float dLo = c0 * aD0 + c1 * aD1;
            float sHi = c2 * aS0 + c3 * aS1;
            float dHi = c2 * aD0 + c3 * aD1;
#pragma unroll
            for (int o = 1; o <= 2; o <<= 1) {
                sLo += __shfl_xor_sync(0xffffffffu, sLo, o);
                dLo += __shfl_xor_sync(0xffffffffu, dLo, o);
                sHi += __shfl_xor_sync(0xffffffffu, sHi, o);
                dHi += __shfl_xor_sync(0xffffffffu, dHi, o);
            }
            if (q == 0) {
                if (rlo < NN) { g_as1[rlo * 8 + n8] = sLo; g_ad1[rlo * 8 + n8] = dLo; }
                if (rhi < NN) { g_as1[rhi * 8 + n8] = sHi; g_ad1[rhi * 8 + n8] = dHi; }
            }
        }
    }
}

// ---------------- layer1 aggregation: SINGLE PASS, warp per dst node ----------
// lane = (eg 0..3) x (head c 0..7); edge loop unrolled x2 -> 8 edges in flight.
__global__ void k_agg1(const float* __restrict__ b1) {
    int n = (blockIdx.x * blockDim.x + threadIdx.x) >> 5;
    int lane = threadIdx.x & 31;
    if (n >= NN) return;
    int eg = lane >> 3;
    int c  = lane & 7;
    int beg = g_rowp[n], end = g_rowp[n + 1];

    float myad = g_ad1[n * 8 + c];
    float den = 0.f;
    float a[8] = {};

    int j = beg + eg;
    for (; j + 4 < end; j += 8) {
        int s0 = g_esrc[j];
        int s1 = g_esrc[j + 4];
        float x0 = g_as1[s0 * 8 + c];
        float x1 = g_as1[s1 * 8 + c];
        uint4 u0 = *(const uint4*)(g_h1h + (size_t)s0 * 64 + c * 8);
        uint4 u1 = *(const uint4*)(g_h1h + (size_t)s1 * 64 + c * 8);
        float e0 = lrelu_exp(x0 + myad);
        float e1 = lrelu_exp(x1 + myad);
        den += e0 + e1;
        float2 f;
        f = __half22float2(*(const __half2*)&u0.x); a[0] += e0 * f.x; a[1] += e0 * f.y;
        f = __half22float2(*(const __half2*)&u0.y); a[2] += e0 * f.x; a[3] += e0 * f.y;
        f = __half22float2(*(const __half2*)&u0.z); a[4] += e0 * f.x; a[5] += e0 * f.y;
        f = __half22float2(*(const __half2*)&u0.w); a[6] += e0 * f.x; a[7] += e0 * f.y;
        f = __half22float2(*(const __half2*)&u1.x); a[0] += e1 * f.x; a[1] += e1 * f.y;
        f = __half22float2(*(const __half2*)&u1.y); a[2] += e1 * f.x; a[3] += e1 * f.y;
        f = __half22float2(*(const __half2*)&u1.z); a[4] += e1 * f.x; a[5] += e1 * f.y;
        f = __half22float2(*(const __half2*)&u1.w); a[6] += e1 * f.x; a[7] += e1 * f.y;
    }
    if (j < end) {
        int s0 = g_esrc[j];
        float e0 = lrelu_exp(g_as1[s0 * 8 + c] + myad);
        uint4 u0 = *(const uint4*)(g_h1h + (size_t)s0 * 64 + c * 8);
        den += e0;
        float2 f;
        f = __half22float2(*(const __half2*)&u0.x); a[0] += e0 * f.x; a[1] += e0 * f.y;
        f = __half22float2(*(const __half2*)&u0.y); a[2] += e0 * f.x; a[3] += e0 * f.y;
        f = __half22float2(*(const __half2*)&u0.z); a[4] += e0 * f.x; a[5] += e0 * f.y;
        f = __half22float2(*(const __half2*)&u0.w); a[6] += e0 * f.x; a[7] += e0 * f.y;
    }

#pragma unroll
    for (int o = 8; o <= 16; o <<= 1) {
        den += __shfl_xor_sync(0xffffffffu, den, o);
#pragma unroll
        for (int i = 0; i < 8; i++)
            a[i] += __shfl_xor_sync(0xffffffffu, a[i], o);
    }

    if (eg == 0) {
        float rden = 1.0f / (den + 1e-16f);
        float* op = g_out1 + (size_t)n * 64 + c * 8;
        const float* bp = b1 + c * 8;
        float4 o0, o1;
        o0.x = fmaxf(a[0] * rden + __ldg(bp + 0), 0.f);
        o0.y = fmaxf(a[1] * rden + __ldg(bp + 1), 0.f);
        o0.z = fmaxf(a[2] * rden + __ldg(bp + 2), 0.f);
        o0.w = fmaxf(a[3] * rden + __ldg(bp + 3), 0.f);
        o1.x = fmaxf(a[4] * rden + __ldg(bp + 4), 0.f);
        o1.y = fmaxf(a[5] * rden + __ldg(bp + 5), 0.f);
        o1.z = fmaxf(a[6] * rden + __ldg(bp + 6), 0.f);
        o1.w = fmaxf(a[7] * rden + __ldg(bp + 7), 0.f);
        *(float4*)(op)     = o0;
        *(float4*)(op + 4) = o1;
    }
}

// ---------------- layer2 node phase: out1 @ W2, a2 ----------------------------
__global__ void k_l2(const float* __restrict__ W2,
                     const float* __restrict__ aS2, const float* __restrict__ aD2) {
    __shared__ float Wsm[64 * 40];
    __shared__ float aSs[40], aDs[40];
    int t = threadIdx.x;
    for (int i = t; i < 64 * 40; i += 128) Wsm[i] = W2[i];
    if (t < 40) { aSs[t] = aS2[t]; aDs[t] = aD2[t]; }
    __syncthreads();
    int n = blockIdx.x * 128 + t;
    if (n >= NN) return;
    float acc[40] = {};
    const float* r = g_out1 + (size_t)n * 64;
#pragma unroll
    for (int k4 = 0; k4 < 16; k4++) {
        float4 v = *(const float4*)(r + k4 * 4);
#pragma unroll
        for (int c = 0; c < 40; c++) {
            acc[c] += v.x * Wsm[(4 * k4 + 0) * 40 + c]
                    + v.y * Wsm[(4 * k4 + 1) * 40 + c]
                    + v.z * Wsm[(4 * k4 + 2) * 40 + c]
                    + v.w * Wsm[(4 * k4 + 3) * 40 + c];
        }
    }
    float s2 = 0.f, d2 = 0.f;
    __half2* hp = (__half2*)(g_h2h + (size_t)n * 40);
#pragma unroll
    for (int c = 0; c < 20; c++) {
        hp[c] = __floats2half2_rn(acc[2 * c], acc[2 * c + 1]);
        s2 += acc[2 * c] * aSs[2 * c] + acc[2 * c + 1] * aSs[2 * c + 1];
        d2 += acc[2 * c] * aDs[2 * c] + acc[2 * c + 1] * aDs[2 * c + 1];
    }
    g_as2[n] = s2;
    g_ad2[n] = d2;
}

// ---------------- layer2 aggregation: SINGLE PASS + bias + log_softmax --------
// lane = (eg 0..3) x (c 0..7); edge loop unrolled x2.
__global__ void k_agg2(const float* __restrict__ b2, float* __restrict__ out) {
    int n = (blockIdx.x * blockDim.x + threadIdx.x) >> 5;
    int lane = threadIdx.x & 31;
    if (n >= NN) return;
    int eg = lane >> 3;
    int c  = lane & 7;
    int beg = g_rowp[n], end = g_rowp[n + 1];
    float myad = g_ad2[n];

    float den = 0.f;
    float a0 = 0.f, a1 = 0.f, a2 = 0.f, a3 = 0.f, a4 = 0.f, a5 = 0.f;
    int j = beg + eg;
    for (; j + 4 < end; j += 8) {
        int s0 = g_esrc[j];
        int s1 = g_esrc[j + 4];
        float x0 = g_as2[s0];
        float x1 = g_as2[s1];
        const __half2* hp0 = (const __half2*)(g_h2h + (size_t)s0 * 40);
        const __half2* hp1 = (const __half2*)(g_h2h + (size_t)s1 * 40);
        __half2 p0a = hp0[c], p0b = hp0[c + 8];
        __half2 p1a = hp1[c], p1b = hp1[c + 8];
        float e0 = lrelu_exp(x0 + myad);
        float e1 = lrelu_exp(x1 + myad);
        den += e0 + e1;
        float2 f;
        f = __half22float2(p0a); a0 += e0 * f.x; a1 += e0 * f.y;
        f = __half22float2(p0b); a2 += e0 * f.x; a3 += e0 * f.y;
        f = __half22float2(p1a); a0 += e1 * f.x; a1 += e1 * f.y;
        f = __half22float2(p1b); a2 += e1 * f.x; a3 += e1 * f.y;
        if (c < 4) {
            f = __half22float2(hp0[c + 16]); a4 += e0 * f.x; a5 += e0 * f.y;
            f = __half22float2(hp1[c + 16]); a4 += e1 * f.x; a5 += e1 * f.y;
        }
    }
    if (j < end) {
        int s0 = g_esrc[j];
        float e0 = lrelu_exp(g_as2[s0] + myad);
        den += e0;
        const __half2* hp0 = (const __half2*)(g_h2h + (size_t)s0 * 40);
        float2 f;
        f = __half22float2(hp0[c]);     a0 += e0 * f.x; a1 += e0 * f.y;
        f = __half22float2(hp0[c + 8]); a2 += e0 * f.x; a3 += e0 * f.y;
        if (c < 4) {
            f = __half22float2(hp0[c + 16]); a4 += e0 * f.x; a5 += e0 * f.y;
        }
    }
#pragma unroll
    for (int o = 8; o <= 16; o <<= 1) {
        den += __shfl_xor_sync(0xffffffffu, den, o);
        a0  += __shfl_xor_sync(0xffffffffu, a0, o);
        a1  += __shfl_xor_sync(0xffffffffu, a1, o);
        a2  += __shfl_xor_sync(0xffffffffu, a2, o);
        a3  += __shfl_xor_sync(0xffffffffu, a3, o);
        a4  += __shfl_xor_sync(0xffffffffu, a4, o);
        a5  += __shfl_xor_sync(0xffffffffu, a5, o);
    }
    float rden = 1.0f / (den + 1e-16f);

    float v0 = a0 * rden + __ldg(b2 + 2 * c);
    float v1 = a1 * rden + __ldg(b2 + 2 * c + 1);
    float v2 = a2 * rden + __ldg(b2 + 2 * c + 16);
    float v3 = a3 * rden + __ldg(b2 + 2 * c + 17);
    float v4 = -FLT_MAX, v5 = -FLT_MAX;
    if (c < 4) {
        v4 = a4 * rden + __ldg(b2 + 2 * c + 32);
        v5 = a5 * rden + __ldg(b2 + 2 * c + 33);
    }
    float m = fmaxf(fmaxf(fmaxf(v0, v1), fmaxf(v2, v3)), fmaxf(v4, v5));
#pragma unroll
    for (int o = 16; o > 0; o >>= 1)
        m = fmaxf(m, __shfl_xor_sync(0xffffffffu, m, o));
    float sum = 0.f;
    if (eg == 0) {
        sum = __expf(v0 - m) + __expf(v1 - m) + __expf(v2 - m) + __expf(v3 - m);
        if (c < 4) sum += __expf(v4 - m) + __expf(v5 - m);
    }
#pragma unroll
    for (int o = 16; o > 0; o >>= 1)
        sum += __shfl_xor_sync(0xffffffffu, sum, o);
    float ls = m + logf(sum);
    if (eg == 0) {
        float* op = out + (size_t)n * 40;
        float2 w0; w0.x = v0 - ls; w0.y = v1 - ls;
        float2 w1; w1.x = v2 - ls; w1.y = v3 - ls;
        *(float2*)(op + 2 * c)      = w0;
        *(float2*)(op + 2 * c + 16) = w1;
        if (c < 4) {
            float2 w2; w2.x = v4 - ls; w2.y = v5 - ls;
            *(float2*)(op + 2 * c + 32) = w2;
        }
    }
}

// ------------------------------------------------------------------------------
static cudaStream_t g_s1;
static cudaEvent_t g_evA, g_evB;
static void* g_degPtr = nullptr;
static bool g_init = false;

extern "C" void kernel_launch(void* const* d_in, const int* in_sizes, int n_in,
                              void* d_out, int out_size) {
    const float* x     = (const float*)d_in[0];
    const int*   ei    = (const int*)d_in[1];
    const float* W1    = (const float*)d_in[2];
    const float* attS1 = (const float*)d_in[3];
    const float* attD1 = (const float*)d_in[4];
    const float* b1    = (const float*)d_in[5];
    const float* W2    = (const float*)d_in[6];
    const float* attS2 = (const float*)d_in[7];
    const float* attD2 = (const float*)d_in[8];
    const float* b2    = (const float*)d_in[9];
    float* out = (float*)d_out;

    if (!g_init) {
        cudaStreamCreateWithFlags(&g_s1, cudaStreamNonBlocking);
        cudaEventCreateWithFlags(&g_evA, cudaEventDisableTiming);
        cudaEventCreateWithFlags(&g_evB, cudaEventDisableTiming);
        cudaGetSymbolAddress(&g_degPtr, g_deg);
        g_init = true;
    }

    int E = in_sizes[1] / 2;
    if (E > EMAX) E = EMAX;
    int ET = E + NN;

    // fork: CSR build on g_s1, GEMM1 on the main (null) stream
    cudaEventRecord(g_evA, 0);
    cudaStreamWaitEvent(g_s1, g_evA, 0);

    cudaMemsetAsync(g_degPtr, 0, NN * sizeof(int), g_s1);
    {
        int thr = (ET + 7) / 8;
        k_decode<<<(thr + 255) / 256, 256, 0, g_s1>>>(ei, E);
    }
    k_scan<<<1, 1024, 0, g_s1>>>(ET);
    {
        int thr = (ET + 7) / 8;
        k_scatter<<<(thr + 255) / 256, 256, 0, g_s1>>>(ei, E);
    }
    cudaEventRecord(g_evB, g_s1);

    k_gemm1<<<(NN + 255) / 256, 256>>>(x, W1, attS1, attD1);

    // join, then the dependent chain
    cudaStreamWaitEvent(0, g_evB, 0);
    k_agg1<<<(NN * 32 + 255) / 256, 256>>>(b1);
    k_l2<<<(NN + 127) / 128, 128>>>(W2, attS2, attD2);
    k_agg2<<<(NN * 32 + 255) / 256, 256>>>(b2, out);
}